// round 1
// baseline (speedup 1.0000x reference)
#include <cuda_runtime.h>
#include <math.h>

// Problem constants
#define B_  4
#define N_  4096
#define U_  512
#define M1  (B_ * N_)            // 16384 rows for projections

// SGEMM tiling
#define BM 128
#define BN 128
#define BK 8

// Scratch (device globals — no allocation allowed)
__device__ float g_Q[(size_t)B_ * N_ * U_];
__device__ float g_K[(size_t)B_ * N_ * U_];
__device__ float g_V[(size_t)B_ * N_ * U_];
__device__ float g_S[(size_t)B_ * N_ * N_];   // 256 MB scores/probs
__device__ float g_C[(size_t)B_ * N_ * U_];   // ctx

// ---------------------------------------------------------------------------
// Generic tiled SGEMM:
//   C[z] = scale * (A[z] x B[z or B^T[z]]) + bias + residual[z]
// A: row-major [M,K]; B: row-major [K,N] (TRANSB=false) or [N,K] (TRANSB=true)
// All of M,N divisible by 128, K divisible by 8 for this problem.
// ---------------------------------------------------------------------------
template <bool TRANSB>
__global__ __launch_bounds__(256)
void sgemm_kernel(const float* __restrict__ A,
                  const float* __restrict__ Bm,
                  const float* __restrict__ bias,      // [N] or null
                  const float* __restrict__ residual,  // [M,N] or null
                  float* __restrict__ C,
                  int M, int N, int K,
                  long long sA, long long sB, long long sC,
                  float scale)
{
    const int z = blockIdx.z;
    A  += (long long)z * sA;
    Bm += (long long)z * sB;
    C  += (long long)z * sC;
    if (residual) residual += (long long)z * sC;

    __shared__ float As[BK][BM];
    __shared__ float Bs[BK][BN];

    const int tid = threadIdx.x;           // 0..255
    const int tx  = tid & 15;              // 0..15  (N dir)
    const int ty  = tid >> 4;              // 0..15  (M dir)

    const int rowBase = blockIdx.y * BM;
    const int colBase = blockIdx.x * BN;

    float acc[8][8];
    #pragma unroll
    for (int i = 0; i < 8; i++)
        #pragma unroll
        for (int j = 0; j < 8; j++)
            acc[i][j] = 0.0f;

    // A tile loader indices: 128 rows x 8 cols, float4 per thread
    const int aRow = tid >> 1;             // 0..127
    const int aCol = (tid & 1) * 4;        // 0 or 4

    // B tile loader indices
    // NN: 8 rows (k) x 128 cols (n): bRow=k, bCol4=n
    const int bRowNN = tid >> 5;           // 0..7
    const int bColNN = (tid & 31) * 4;     // 0..124
    // NT: 128 rows (n) x 8 cols (k)
    const int bRowNT = tid >> 1;           // 0..127 (n)
    const int bColNT = (tid & 1) * 4;      // 0 or 4 (k)

    for (int k0 = 0; k0 < K; k0 += BK) {
        // ---- load A tile (transpose into As[k][m]) ----
        {
            float4 a = *reinterpret_cast<const float4*>(
                &A[(long long)(rowBase + aRow) * K + k0 + aCol]);
            As[aCol + 0][aRow] = a.x;
            As[aCol + 1][aRow] = a.y;
            As[aCol + 2][aRow] = a.z;
            As[aCol + 3][aRow] = a.w;
        }
        // ---- load B tile ----
        if (!TRANSB) {
            float4 b = *reinterpret_cast<const float4*>(
                &Bm[(long long)(k0 + bRowNN) * N + colBase + bColNN]);
            *reinterpret_cast<float4*>(&Bs[bRowNN][bColNN]) = b;
        } else {
            float4 b = *reinterpret_cast<const float4*>(
                &Bm[(long long)(colBase + bRowNT) * K + k0 + bColNT]);
            Bs[bColNT + 0][bRowNT] = b.x;
            Bs[bColNT + 1][bRowNT] = b.y;
            Bs[bColNT + 2][bRowNT] = b.z;
            Bs[bColNT + 3][bRowNT] = b.w;
        }
        __syncthreads();

        // ---- compute ----
        #pragma unroll
        for (int kk = 0; kk < BK; kk++) {
            float a[8], b[8];
            float4 a0 = *reinterpret_cast<const float4*>(&As[kk][ty * 8]);
            float4 a1 = *reinterpret_cast<const float4*>(&As[kk][ty * 8 + 4]);
            float4 b0 = *reinterpret_cast<const float4*>(&Bs[kk][tx * 8]);
            float4 b1 = *reinterpret_cast<const float4*>(&Bs[kk][tx * 8 + 4]);
            a[0]=a0.x; a[1]=a0.y; a[2]=a0.z; a[3]=a0.w;
            a[4]=a1.x; a[5]=a1.y; a[6]=a1.z; a[7]=a1.w;
            b[0]=b0.x; b[1]=b0.y; b[2]=b0.z; b[3]=b0.w;
            b[4]=b1.x; b[5]=b1.y; b[6]=b1.z; b[7]=b1.w;
            #pragma unroll
            for (int i = 0; i < 8; i++)
                #pragma unroll
                for (int j = 0; j < 8; j++)
                    acc[i][j] = fmaf(a[i], b[j], acc[i][j]);
        }
        __syncthreads();
    }

    // ---- epilogue ----
    #pragma unroll
    for (int i = 0; i < 8; i++) {
        const int row = rowBase + ty * 8 + i;
        const int col = colBase + tx * 8;
        float out[8];
        #pragma unroll
        for (int j = 0; j < 8; j++) out[j] = acc[i][j] * scale;
        if (bias) {
            #pragma unroll
            for (int j = 0; j < 8; j++) out[j] += bias[col + j];
        }
        if (residual) {
            float4 r0 = *reinterpret_cast<const float4*>(&residual[(long long)row * N + col]);
            float4 r1 = *reinterpret_cast<const float4*>(&residual[(long long)row * N + col + 4]);
            out[0]+=r0.x; out[1]+=r0.y; out[2]+=r0.z; out[3]+=r0.w;
            out[4]+=r1.x; out[5]+=r1.y; out[6]+=r1.z; out[7]+=r1.w;
        }
        float4 o0 = make_float4(out[0], out[1], out[2], out[3]);
        float4 o1 = make_float4(out[4], out[5], out[6], out[7]);
        *reinterpret_cast<float4*>(&C[(long long)row * N + col])     = o0;
        *reinterpret_cast<float4*>(&C[(long long)row * N + col + 4]) = o1;
    }
}

// ---------------------------------------------------------------------------
// Row softmax in place: one block (256 threads) per row of 4096 elements.
// 16 elements per thread kept in registers (4x float4).
// ---------------------------------------------------------------------------
__global__ __launch_bounds__(256)
void softmax_kernel(float* __restrict__ S, int cols)
{
    const long long row = blockIdx.x;
    float4* r = reinterpret_cast<float4*>(S + row * (long long)cols);
    const int tid = threadIdx.x;

    __shared__ float red[256];

    float4 v[4];
    float m = -INFINITY;
    #pragma unroll
    for (int i = 0; i < 4; i++) {
        v[i] = r[tid + i * 256];
        m = fmaxf(m, fmaxf(fmaxf(v[i].x, v[i].y), fmaxf(v[i].z, v[i].w)));
    }

    // block max
    red[tid] = m; __syncthreads();
    #pragma unroll
    for (int s = 128; s > 0; s >>= 1) {
        if (tid < s) red[tid] = fmaxf(red[tid], red[tid + s]);
        __syncthreads();
    }
    m = red[0];
    __syncthreads();

    float sum = 0.0f;
    #pragma unroll
    for (int i = 0; i < 4; i++) {
        v[i].x = expf(v[i].x - m); v[i].y = expf(v[i].y - m);
        v[i].z = expf(v[i].z - m); v[i].w = expf(v[i].w - m);
        sum += v[i].x + v[i].y + v[i].z + v[i].w;
    }

    // block sum
    red[tid] = sum; __syncthreads();
    #pragma unroll
    for (int s = 128; s > 0; s >>= 1) {
        if (tid < s) red[tid] += red[tid + s];
        __syncthreads();
    }
    const float inv = 1.0f / red[0];

    #pragma unroll
    for (int i = 0; i < 4; i++) {
        v[i].x *= inv; v[i].y *= inv; v[i].z *= inv; v[i].w *= inv;
        r[tid + i * 256] = v[i];
    }
}

// ---------------------------------------------------------------------------
extern "C" void kernel_launch(void* const* d_in, const int* in_sizes, int n_in,
                              void* d_out, int out_size)
{
    const float* x  = (const float*)d_in[0];
    const float* Wq = (const float*)d_in[1];
    const float* bq = (const float*)d_in[2];
    const float* Wk = (const float*)d_in[3];
    const float* bk = (const float*)d_in[4];
    const float* Wv = (const float*)d_in[5];
    const float* bv = (const float*)d_in[6];
    const float* Wp = (const float*)d_in[7];
    const float* bp = (const float*)d_in[8];
    float* out = (float*)d_out;

    float *Q, *K, *V, *S, *C;
    cudaGetSymbolAddress((void**)&Q, g_Q);
    cudaGetSymbolAddress((void**)&K, g_K);
    cudaGetSymbolAddress((void**)&V, g_V);
    cudaGetSymbolAddress((void**)&S, g_S);
    cudaGetSymbolAddress((void**)&C, g_C);

    const float scale = 1.0f / sqrtf((float)U_);  // 1/sqrt(512)

    // 1) Q, K, V projections: [16384,512] = x[16384,512] @ W[512,512] + b
    {
        dim3 grid(U_ / BN, M1 / BM, 1);
        sgemm_kernel<false><<<grid, 256>>>(x, Wq, bq, nullptr, Q,
                                           M1, U_, U_, 0, 0, 0, 1.0f);
        sgemm_kernel<false><<<grid, 256>>>(x, Wk, bk, nullptr, K,
                                           M1, U_, U_, 0, 0, 0, 1.0f);
        sgemm_kernel<false><<<grid, 256>>>(x, Wv, bv, nullptr, V,
                                           M1, U_, U_, 0, 0, 0, 1.0f);
    }

    // 2) S[b] = scale * Q[b] @ K[b]^T   ([4096,4096] per batch)
    {
        dim3 grid(N_ / BN, N_ / BM, B_);
        sgemm_kernel<true><<<grid, 256>>>(Q, K, nullptr, nullptr, S,
                                          N_, N_, U_,
                                          (long long)N_ * U_, (long long)N_ * U_,
                                          (long long)N_ * N_, scale);
    }

    // 3) row softmax in place
    softmax_kernel<<<B_ * N_, 256>>>(S, N_);

    // 4) ctx[b] = P[b] @ V[b]   ([4096,512] per batch, K=4096)
    {
        dim3 grid(U_ / BN, N_ / BM, B_);
        sgemm_kernel<false><<<grid, 256>>>(S, V, nullptr, nullptr, C,
                                           N_, U_, N_,
                                           (long long)N_ * N_, (long long)N_ * U_,
                                           (long long)N_ * U_, 1.0f);
    }

    // 5) out = x + ctx @ Wp + bp
    {
        dim3 grid(U_ / BN, M1 / BM, 1);
        sgemm_kernel<false><<<grid, 256>>>(C, Wp, bp, x, out,
                                           M1, U_, U_, 0, 0, 0, 1.0f);
    }
}

// round 2
// speedup vs baseline: 2.8018x; 2.8018x over previous
#include <cuda_runtime.h>
#include <math.h>
#include <stdint.h>

// Problem constants
#define B_  4
#define N_  4096
#define U_  512
#define M1  (B_ * N_)            // 16384 rows for projections

// GEMM tiling
#define BM 128
#define BN 128
#define BK 32
#define KPAD 36                  // 32 + 4 pad -> conflict-free fragment loads

// Scratch (device globals — no allocation allowed)
__device__ float g_Q [(size_t)B_ * N_ * U_];
__device__ float g_K [(size_t)B_ * N_ * U_];
__device__ float g_V [(size_t)B_ * N_ * U_];
__device__ float g_VT[(size_t)B_ * N_ * U_];   // V transposed per batch [U, N]
__device__ float g_S [(size_t)B_ * N_ * N_];   // 256 MB scores/probs
__device__ float g_C [(size_t)B_ * N_ * U_];   // ctx
__device__ float g_WT[(size_t)4 * U_ * U_];    // Wq^T, Wk^T, Wv^T, Wp^T

// ---------------------------------------------------------------------------
__device__ __forceinline__ uint32_t f2tf32(float x) {
    uint32_t r;
    asm("cvt.rna.tf32.f32 %0, %1;" : "=r"(r) : "f"(x));
    return r;
}

__device__ __forceinline__ void mma_tf32(float c[4],
                                         uint32_t a0, uint32_t a1, uint32_t a2, uint32_t a3,
                                         uint32_t b0, uint32_t b1) {
    asm volatile(
        "mma.sync.aligned.m16n8k8.row.col.f32.tf32.tf32.f32 "
        "{%0,%1,%2,%3}, {%4,%5,%6,%7}, {%8,%9}, {%0,%1,%2,%3};\n"
        : "+f"(c[0]), "+f"(c[1]), "+f"(c[2]), "+f"(c[3])
        : "r"(a0), "r"(a1), "r"(a2), "r"(a3), "r"(b0), "r"(b1));
}

// ---------------------------------------------------------------------------
// NT GEMM on tensor cores (TF32):
//   C[z][m][n] = scale * sum_k A[z][m][k] * B[z][n][k]  (+ bias[n]) (+ residual)
// A: [M,K] row-major, B: [N,K] row-major. M,N % 128 == 0, K % 32 == 0.
// ---------------------------------------------------------------------------
__global__ __launch_bounds__(256)
void gemm_nt_tc(const float* __restrict__ A,
                const float* __restrict__ Bm,
                const float* __restrict__ bias,      // [N] or null
                const float* __restrict__ residual,  // [M,N] or null
                float* __restrict__ C,
                int M, int N, int K,
                long long sA, long long sB, long long sC,
                float scale)
{
    const int z = blockIdx.z;
    A  += (long long)z * sA;
    Bm += (long long)z * sB;
    C  += (long long)z * sC;
    if (residual) residual += (long long)z * sC;

    __shared__ uint32_t As[BM][KPAD];
    __shared__ uint32_t Bs[BN][KPAD];

    const int tid  = threadIdx.x;
    const int lane = tid & 31;
    const int wid  = tid >> 5;
    const int gid  = lane >> 2;   // 0..7
    const int tig  = lane & 3;    // 0..3
    const int warpM = (wid & 1) * 64;   // 2 warps in M
    const int warpN = (wid >> 1) * 32;  // 4 warps in N

    const int rowBase = blockIdx.y * BM;
    const int colBase = blockIdx.x * BN;

    // gmem loader mapping: 4 iterations, each warp loads 4 full consecutive rows
    const int lr = tid >> 3;        // 0..31 (row within group of 32)
    const int lc = (tid & 7) * 4;   // float column 0,4,...,28

    float acc[4][4][4];
    #pragma unroll
    for (int mi = 0; mi < 4; mi++)
        #pragma unroll
        for (int ni = 0; ni < 4; ni++)
            #pragma unroll
            for (int r = 0; r < 4; r++)
                acc[mi][ni][r] = 0.0f;

    const float* Aptr = A + (long long)rowBase * K;
    const float* Bptr = Bm + (long long)colBase * K;

    float4 pa[4], pb[4];
    #pragma unroll
    for (int i = 0; i < 4; i++) {
        pa[i] = *reinterpret_cast<const float4*>(&Aptr[(long long)(lr + i * 32) * K + lc]);
        pb[i] = *reinterpret_cast<const float4*>(&Bptr[(long long)(lr + i * 32) * K + lc]);
    }

    const int nIter = K / BK;
    for (int t = 0; t < nIter; t++) {
        // commit prefetched tile to smem (convert to tf32)
        #pragma unroll
        for (int i = 0; i < 4; i++) {
            uint4 ca, cb;
            ca.x = f2tf32(pa[i].x); ca.y = f2tf32(pa[i].y);
            ca.z = f2tf32(pa[i].z); ca.w = f2tf32(pa[i].w);
            cb.x = f2tf32(pb[i].x); cb.y = f2tf32(pb[i].y);
            cb.z = f2tf32(pb[i].z); cb.w = f2tf32(pb[i].w);
            *reinterpret_cast<uint4*>(&As[lr + i * 32][lc]) = ca;
            *reinterpret_cast<uint4*>(&Bs[lr + i * 32][lc]) = cb;
        }
        __syncthreads();

        // prefetch next tile
        if (t + 1 < nIter) {
            const int k0 = (t + 1) * BK;
            #pragma unroll
            for (int i = 0; i < 4; i++) {
                pa[i] = *reinterpret_cast<const float4*>(&Aptr[(long long)(lr + i * 32) * K + k0 + lc]);
                pb[i] = *reinterpret_cast<const float4*>(&Bptr[(long long)(lr + i * 32) * K + k0 + lc]);
            }
        }

        // compute: 4 k-steps of 8
        #pragma unroll
        for (int kk = 0; kk < 4; kk++) {
            const int kb = kk * 8;
            uint32_t a[4][4], b[4][2];
            #pragma unroll
            for (int mi = 0; mi < 4; mi++) {
                const int mr = warpM + mi * 16;
                a[mi][0] = As[mr + gid    ][kb + tig];
                a[mi][1] = As[mr + gid + 8][kb + tig];
                a[mi][2] = As[mr + gid    ][kb + tig + 4];
                a[mi][3] = As[mr + gid + 8][kb + tig + 4];
            }
            #pragma unroll
            for (int ni = 0; ni < 4; ni++) {
                const int nr = warpN + ni * 8;
                b[ni][0] = Bs[nr + gid][kb + tig];
                b[ni][1] = Bs[nr + gid][kb + tig + 4];
            }
            #pragma unroll
            for (int mi = 0; mi < 4; mi++)
                #pragma unroll
                for (int ni = 0; ni < 4; ni++)
                    mma_tf32(acc[mi][ni], a[mi][0], a[mi][1], a[mi][2], a[mi][3],
                             b[ni][0], b[ni][1]);
        }
        __syncthreads();
    }

    // ---- epilogue ----
    #pragma unroll
    for (int mi = 0; mi < 4; mi++) {
        #pragma unroll
        for (int ni = 0; ni < 4; ni++) {
            const int row0 = rowBase + warpM + mi * 16 + gid;
            const int col  = colBase + warpN + ni * 8 + tig * 2;
            float v[4];
            #pragma unroll
            for (int r = 0; r < 4; r++) v[r] = acc[mi][ni][r] * scale;
            if (bias) {
                const float b0 = bias[col], b1 = bias[col + 1];
                v[0] += b0; v[1] += b1; v[2] += b0; v[3] += b1;
            }
            if (residual) {
                float2 r0 = *reinterpret_cast<const float2*>(&residual[(long long)row0 * N + col]);
                float2 r1 = *reinterpret_cast<const float2*>(&residual[(long long)(row0 + 8) * N + col]);
                v[0] += r0.x; v[1] += r0.y; v[2] += r1.x; v[3] += r1.y;
            }
            *reinterpret_cast<float2*>(&C[(long long)row0 * N + col])       = make_float2(v[0], v[1]);
            *reinterpret_cast<float2*>(&C[(long long)(row0 + 8) * N + col]) = make_float2(v[2], v[3]);
        }
    }
}

// ---------------------------------------------------------------------------
// Batched transpose: out[z][c][r] = in[z][r][c].  R,C % 32 == 0.
// ---------------------------------------------------------------------------
__global__ __launch_bounds__(256)
void transpose_kernel(const float* __restrict__ in, float* __restrict__ out,
                      int R, int C, long long sIn, long long sOut)
{
    __shared__ float tile[32][33];
    const int z = blockIdx.z;
    in  += (long long)z * sIn;
    out += (long long)z * sOut;
    const int c0 = blockIdx.x * 32;
    const int r0 = blockIdx.y * 32;
    const int x = threadIdx.x;      // 0..31
    const int y = threadIdx.y;      // 0..7
    #pragma unroll
    for (int i = 0; i < 32; i += 8)
        tile[y + i][x] = in[(long long)(r0 + y + i) * C + c0 + x];
    __syncthreads();
    #pragma unroll
    for (int i = 0; i < 32; i += 8)
        out[(long long)(c0 + y + i) * R + r0 + x] = tile[x][y + i];
}

// ---------------------------------------------------------------------------
// Row softmax in place: one block (256 threads) per row of 4096 elements.
// ---------------------------------------------------------------------------
__global__ __launch_bounds__(256)
void softmax_kernel(float* __restrict__ S, int cols)
{
    const long long row = blockIdx.x;
    float4* r = reinterpret_cast<float4*>(S + row * (long long)cols);
    const int tid = threadIdx.x;

    __shared__ float red[256];

    float4 v[4];
    float m = -INFINITY;
    #pragma unroll
    for (int i = 0; i < 4; i++) {
        v[i] = r[tid + i * 256];
        m = fmaxf(m, fmaxf(fmaxf(v[i].x, v[i].y), fmaxf(v[i].z, v[i].w)));
    }

    red[tid] = m; __syncthreads();
    #pragma unroll
    for (int s = 128; s > 0; s >>= 1) {
        if (tid < s) red[tid] = fmaxf(red[tid], red[tid + s]);
        __syncthreads();
    }
    m = red[0];
    __syncthreads();

    float sum = 0.0f;
    #pragma unroll
    for (int i = 0; i < 4; i++) {
        v[i].x = expf(v[i].x - m); v[i].y = expf(v[i].y - m);
        v[i].z = expf(v[i].z - m); v[i].w = expf(v[i].w - m);
        sum += v[i].x + v[i].y + v[i].z + v[i].w;
    }

    red[tid] = sum; __syncthreads();
    #pragma unroll
    for (int s = 128; s > 0; s >>= 1) {
        if (tid < s) red[tid] += red[tid + s];
        __syncthreads();
    }
    const float inv = 1.0f / red[0];

    #pragma unroll
    for (int i = 0; i < 4; i++) {
        v[i].x *= inv; v[i].y *= inv; v[i].z *= inv; v[i].w *= inv;
        r[tid + i * 256] = v[i];
    }
}

// ---------------------------------------------------------------------------
extern "C" void kernel_launch(void* const* d_in, const int* in_sizes, int n_in,
                              void* d_out, int out_size)
{
    const float* x  = (const float*)d_in[0];
    const float* Wq = (const float*)d_in[1];
    const float* bq = (const float*)d_in[2];
    const float* Wk = (const float*)d_in[3];
    const float* bk = (const float*)d_in[4];
    const float* Wv = (const float*)d_in[5];
    const float* bv = (const float*)d_in[6];
    const float* Wp = (const float*)d_in[7];
    const float* bp = (const float*)d_in[8];
    float* out = (float*)d_out;

    float *Q, *K, *V, *VT, *S, *C, *WT;
    cudaGetSymbolAddress((void**)&Q,  g_Q);
    cudaGetSymbolAddress((void**)&K,  g_K);
    cudaGetSymbolAddress((void**)&V,  g_V);
    cudaGetSymbolAddress((void**)&VT, g_VT);
    cudaGetSymbolAddress((void**)&S,  g_S);
    cudaGetSymbolAddress((void**)&C,  g_C);
    cudaGetSymbolAddress((void**)&WT, g_WT);

    float* WqT = WT + 0 * (size_t)U_ * U_;
    float* WkT = WT + 1 * (size_t)U_ * U_;
    float* WvT = WT + 2 * (size_t)U_ * U_;
    float* WpT = WT + 3 * (size_t)U_ * U_;

    const float scale = 1.0f / sqrtf((float)U_);

    dim3 tb(32, 8, 1);

    // 0) transpose weights
    {
        dim3 grid(U_ / 32, U_ / 32, 1);
        transpose_kernel<<<grid, tb>>>(Wq, WqT, U_, U_, 0, 0);
        transpose_kernel<<<grid, tb>>>(Wk, WkT, U_, U_, 0, 0);
        transpose_kernel<<<grid, tb>>>(Wv, WvT, U_, U_, 0, 0);
        transpose_kernel<<<grid, tb>>>(Wp, WpT, U_, U_, 0, 0);
    }

    // 1) Q, K, V projections: [16384,512] = x @ W + b   (NT with W^T)
    {
        dim3 grid(U_ / BN, M1 / BM, 1);
        gemm_nt_tc<<<grid, 256>>>(x, WqT, bq, nullptr, Q, M1, U_, U_, 0, 0, 0, 1.0f);
        gemm_nt_tc<<<grid, 256>>>(x, WkT, bk, nullptr, K, M1, U_, U_, 0, 0, 0, 1.0f);
        gemm_nt_tc<<<grid, 256>>>(x, WvT, bv, nullptr, V, M1, U_, U_, 0, 0, 0, 1.0f);
    }

    // 2) V^T per batch: [512, 4096]
    {
        dim3 grid(U_ / 32, N_ / 32, B_);
        transpose_kernel<<<grid, tb>>>(V, VT, N_, U_,
                                       (long long)N_ * U_, (long long)N_ * U_);
    }

    // 3) S[b] = scale * Q[b] @ K[b]^T
    {
        dim3 grid(N_ / BN, N_ / BM, B_);
        gemm_nt_tc<<<grid, 256>>>(Q, K, nullptr, nullptr, S,
                                  N_, N_, U_,
                                  (long long)N_ * U_, (long long)N_ * U_,
                                  (long long)N_ * N_, scale);
    }

    // 4) row softmax in place
    softmax_kernel<<<B_ * N_, 256>>>(S, N_);

    // 5) ctx[b] = P[b] @ V[b]  (NT with V^T: B2[n][k] = V[k][n])
    {
        dim3 grid(U_ / BN, N_ / BM, B_);
        gemm_nt_tc<<<grid, 256>>>(S, VT, nullptr, nullptr, C,
                                  N_, U_, N_,
                                  (long long)N_ * N_, (long long)N_ * U_,
                                  (long long)N_ * U_, 1.0f);
    }

    // 6) out = x + ctx @ Wp + bp  (NT with Wp^T)
    {
        dim3 grid(U_ / BN, M1 / BM, 1);
        gemm_nt_tc<<<grid, 256>>>(C, WpT, bp, x, out, M1, U_, U_, 0, 0, 0, 1.0f);
    }
}

// round 5
// speedup vs baseline: 7.0418x; 2.5133x over previous
#include <cuda_runtime.h>
#include <cuda_bf16.h>
#include <math.h>
#include <stdint.h>

// Problem constants
#define B_  4
#define N_  4096
#define U_  512
#define M1  (B_ * N_)

// GEMM tiling
#define BM 128
#define BN 128
#define BK 64            // bf16 elements per K tile
#define SKB 144          // smem row stride in BYTES (64*2 + 16 pad) -> conflict-free ldmatrix

static constexpr int ATILE = BM * SKB;          // 18432 B
static constexpr int SM_A0 = 0;
static constexpr int SM_B0 = 2 * ATILE;
static constexpr int SM_TOTAL = 4 * ATILE;      // 73728 B

// ---------------- scratch (device globals; no allocation allowed) ----------
__device__ __align__(16) __nv_bfloat16 g_xb[(size_t)M1 * U_];
__device__ __align__(16) __nv_bfloat16 g_Q [(size_t)M1 * U_];
__device__ __align__(16) __nv_bfloat16 g_K [(size_t)M1 * U_];
__device__ __align__(16) __nv_bfloat16 g_V [(size_t)M1 * U_];
__device__ __align__(16) __nv_bfloat16 g_VT[(size_t)M1 * U_];        // per batch [U, N]
__device__ __align__(16) __nv_bfloat16 g_S [(size_t)B_ * N_ * N_];   // 128 MB scores/probs
__device__ __align__(16) __nv_bfloat16 g_C [(size_t)M1 * U_];        // ctx
__device__ __align__(16) __nv_bfloat16 g_WT[(size_t)4 * U_ * U_];    // transposed weights

// ---------------- PTX helpers ----------------------------------------------
__device__ __forceinline__ uint32_t smem_u32(const void* p) {
    uint32_t a;
    asm("{ .reg .u64 t; cvta.to.shared.u64 t, %1; cvt.u32.u64 %0, t; }" : "=r"(a) : "l"(p));
    return a;
}
#define CP_ASYNC16(dst, src) \
    asm volatile("cp.async.cg.shared.global [%0], [%1], 16;\n" :: "r"(dst), "l"(src))
#define CP_COMMIT() asm volatile("cp.async.commit_group;\n" ::: "memory")
#define CP_WAIT(n)  asm volatile("cp.async.wait_group %0;\n" :: "n"(n) : "memory")

__device__ __forceinline__ void ldsm_x4(uint32_t& r0, uint32_t& r1, uint32_t& r2,
                                        uint32_t& r3, uint32_t addr) {
    asm volatile("ldmatrix.sync.aligned.m8n8.x4.shared.b16 {%0,%1,%2,%3}, [%4];"
                 : "=r"(r0), "=r"(r1), "=r"(r2), "=r"(r3) : "r"(addr));
}
__device__ __forceinline__ void mma_bf16(float c[4],
                                         uint32_t a0, uint32_t a1, uint32_t a2, uint32_t a3,
                                         uint32_t b0, uint32_t b1) {
    asm volatile(
        "mma.sync.aligned.m16n8k16.row.col.f32.bf16.bf16.f32 "
        "{%0,%1,%2,%3}, {%4,%5,%6,%7}, {%8,%9}, {%0,%1,%2,%3};\n"
        : "+f"(c[0]), "+f"(c[1]), "+f"(c[2]), "+f"(c[3])
        : "r"(a0), "r"(a1), "r"(a2), "r"(a3), "r"(b0), "r"(b1));
}

// ---------------------------------------------------------------------------
// bf16 NT GEMM (mma.sync m16n8k16 + ldmatrix + cp.async double buffer):
//   C[z] = scale * A[z] @ B[z]^T (+bias) (+residual)
// A: [M,K] bf16 row-major. B: [N,K] bf16 row-major. M,N % 128 == 0, K % 64 == 0.
// ---------------------------------------------------------------------------
template <bool OBF16>
__global__ __launch_bounds__(256, 2)
void gemm_bf16(const __nv_bfloat16* __restrict__ A,
               const __nv_bfloat16* __restrict__ Bm,
               const float* __restrict__ bias,
               const float* __restrict__ residual,
               void* __restrict__ Cout,
               int M, int N, int K,
               long long sA, long long sB, long long sC,
               float scale)
{
    extern __shared__ char smem[];
    const uint32_t sbase = smem_u32(smem);
    const int tid  = threadIdx.x;
    const int wid  = tid >> 5;
    const int lane = tid & 31;

    const int z = blockIdx.z;
    A  += (long long)z * sA;
    Bm += (long long)z * sB;

    const int rowBase = blockIdx.y * BM;
    const int colBase = blockIdx.x * BN;
    const int warpM = (wid & 1) * 64;    // 2 warps in M
    const int warpN = (wid >> 1) * 32;   // 4 warps in N

    const __nv_bfloat16* Aptr = A + (long long)rowBase * K;
    const __nv_bfloat16* Bptr = Bm + (long long)colBase * K;

    float acc[4][4][4];
    #pragma unroll
    for (int mi = 0; mi < 4; mi++)
        #pragma unroll
        for (int ni = 0; ni < 4; ni++)
            #pragma unroll
            for (int r = 0; r < 4; r++)
                acc[mi][ni][r] = 0.0f;

    // cp.async tile loader: 1024 chunks each for A and B, 256 threads
    const int lr = tid >> 3;            // row group base 0..31
    const int lc = tid & 7;             // 16B chunk 0..7
    auto load_tile = [&](int s, int k0) {
        const uint32_t abase = sbase + SM_A0 + s * ATILE;
        const uint32_t bbase = sbase + SM_B0 + s * ATILE;
        #pragma unroll
        for (int i = 0; i < 4; i++) {
            const int r = lr + i * 32;
            CP_ASYNC16(abase + r * SKB + lc * 16,
                       Aptr + (long long)r * K + k0 + lc * 8);
        }
        #pragma unroll
        for (int i = 0; i < 4; i++) {
            const int r = lr + i * 32;
            CP_ASYNC16(bbase + r * SKB + lc * 16,
                       Bptr + (long long)r * K + k0 + lc * 8);
        }
        CP_COMMIT();
    };

    // ldmatrix per-lane address components
    const int lm = lane & 7;
    const int lt = lane >> 3;           // tile index 0..3
    // A: row = +lm + (lt&1)*8, kOff elements = (lt>>1)*8
    const int aRowOff = lm + (lt & 1) * 8;
    const int aKOff   = (lt >> 1) * 8;
    // B: row(n) = +lm + (lt>>1)*8, kOff = (lt&1)*8
    const int bRowOff = lm + (lt >> 1) * 8;
    const int bKOff   = (lt & 1) * 8;

    const int T = K / BK;
    load_tile(0, 0);

    for (int t = 0; t < T; t++) {
        const int s = t & 1;
        if (t + 1 < T) {
            load_tile((t + 1) & 1, (t + 1) * BK);
            CP_WAIT(1);
        } else {
            CP_WAIT(0);
        }
        __syncthreads();

        const uint32_t Asb = sbase + SM_A0 + s * ATILE;
        const uint32_t Bsb = sbase + SM_B0 + s * ATILE;

        #pragma unroll
        for (int kk = 0; kk < 4; kk++) {
            uint32_t a[4][4], b[4][2];
            #pragma unroll
            for (int mi = 0; mi < 4; mi++) {
                uint32_t addr = Asb + (warpM + mi * 16 + aRowOff) * SKB
                              + (kk * 16 + aKOff) * 2;
                ldsm_x4(a[mi][0], a[mi][1], a[mi][2], a[mi][3], addr);
            }
            #pragma unroll
            for (int p = 0; p < 2; p++) {
                uint32_t addr = Bsb + (warpN + p * 16 + bRowOff) * SKB
                              + (kk * 16 + bKOff) * 2;
                uint32_t r0, r1, r2, r3;
                ldsm_x4(r0, r1, r2, r3, addr);
                b[2*p][0] = r0; b[2*p][1] = r1;
                b[2*p+1][0] = r2; b[2*p+1][1] = r3;
            }
            #pragma unroll
            for (int mi = 0; mi < 4; mi++)
                #pragma unroll
                for (int ni = 0; ni < 4; ni++)
                    mma_bf16(acc[mi][ni], a[mi][0], a[mi][1], a[mi][2], a[mi][3],
                             b[ni][0], b[ni][1]);
        }
        __syncthreads();
    }

    // ---- epilogue ----
    #pragma unroll
    for (int mi = 0; mi < 4; mi++) {
        #pragma unroll
        for (int ni = 0; ni < 4; ni++) {
            const int row0 = rowBase + warpM + mi * 16 + (lane >> 2);
            const int col  = colBase + warpN + ni * 8 + (lane & 3) * 2;
            float v[4];
            #pragma unroll
            for (int r = 0; r < 4; r++) v[r] = acc[mi][ni][r] * scale;
            if (bias) {
                const float b0 = bias[col], b1 = bias[col + 1];
                v[0] += b0; v[1] += b1; v[2] += b0; v[3] += b1;
            }
            if (!OBF16) {
                float* C = (float*)Cout + (long long)z * sC;
                if (residual) {
                    const float* R = residual + (long long)z * sC;
                    float2 r0 = *reinterpret_cast<const float2*>(&R[(long long)row0 * N + col]);
                    float2 r1 = *reinterpret_cast<const float2*>(&R[(long long)(row0 + 8) * N + col]);
                    v[0] += r0.x; v[1] += r0.y; v[2] += r1.x; v[3] += r1.y;
                }
                *reinterpret_cast<float2*>(&C[(long long)row0 * N + col])       = make_float2(v[0], v[1]);
                *reinterpret_cast<float2*>(&C[(long long)(row0 + 8) * N + col]) = make_float2(v[2], v[3]);
            } else {
                __nv_bfloat16* C = (__nv_bfloat16*)Cout + (long long)z * sC;
                __nv_bfloat162 p0 = __floats2bfloat162_rn(v[0], v[1]);
                __nv_bfloat162 p1 = __floats2bfloat162_rn(v[2], v[3]);
                *reinterpret_cast<uint32_t*>(&C[(long long)row0 * N + col])       = *(uint32_t*)&p0;
                *reinterpret_cast<uint32_t*>(&C[(long long)(row0 + 8) * N + col]) = *(uint32_t*)&p1;
            }
        }
    }
}

// ---------------------------------------------------------------------------
// fp32 -> bf16 convert (4 elems/thread)
// ---------------------------------------------------------------------------
__global__ __launch_bounds__(256)
void conv_bf16(const float* __restrict__ in, __nv_bfloat16* __restrict__ out, long long n)
{
    long long i = ((long long)blockIdx.x * blockDim.x + threadIdx.x) * 4;
    if (i >= n) return;
    float4 f = *reinterpret_cast<const float4*>(in + i);
    __nv_bfloat162 p0 = __floats2bfloat162_rn(f.x, f.y);
    __nv_bfloat162 p1 = __floats2bfloat162_rn(f.z, f.w);
    uint2 o; o.x = *(uint32_t*)&p0; o.y = *(uint32_t*)&p1;
    *reinterpret_cast<uint2*>(out + i) = o;
}

// fp32 [R,C] -> bf16 transposed [C,R]
__global__ __launch_bounds__(256)
void wtransT(const float* __restrict__ in, __nv_bfloat16* __restrict__ out, int R, int C)
{
    __shared__ float tile[32][33];
    const int c0 = blockIdx.x * 32, r0 = blockIdx.y * 32;
    const int x = threadIdx.x, y = threadIdx.y;
    #pragma unroll
    for (int i = 0; i < 32; i += 8)
        tile[y + i][x] = in[(long long)(r0 + y + i) * C + c0 + x];
    __syncthreads();
    #pragma unroll
    for (int i = 0; i < 32; i += 8)
        out[(long long)(c0 + y + i) * R + r0 + x] = __float2bfloat16(tile[x][y + i]);
}

// bf16 [R,C] per batch -> bf16 [C,R]
__global__ __launch_bounds__(256)
void btransT(const __nv_bfloat16* __restrict__ in, __nv_bfloat16* __restrict__ out,
             int R, int C, long long sIn, long long sOut)
{
    __shared__ __nv_bfloat16 tile[32][34];
    const int z = blockIdx.z;
    in  += (long long)z * sIn;
    out += (long long)z * sOut;
    const int c0 = blockIdx.x * 32, r0 = blockIdx.y * 32;
    const int x = threadIdx.x, y = threadIdx.y;
    #pragma unroll
    for (int i = 0; i < 32; i += 8)
        tile[y + i][x] = in[(long long)(r0 + y + i) * C + c0 + x];
    __syncthreads();
    #pragma unroll
    for (int i = 0; i < 32; i += 8)
        out[(long long)(c0 + y + i) * R + r0 + x] = tile[x][y + i];
}

// ---------------------------------------------------------------------------
// row softmax on bf16 [rows x 4096], in place
// ---------------------------------------------------------------------------
__global__ __launch_bounds__(256)
void softmax_bf16(__nv_bfloat16* __restrict__ S)
{
    const long long row = blockIdx.x;
    uint4* p = reinterpret_cast<uint4*>(S + row * (long long)N_);
    const int tid = threadIdx.x;
    __shared__ float red[256];

    uint4 u[2];
    u[0] = p[tid * 2];
    u[1] = p[tid * 2 + 1];

    float f[16];
    {
        const __nv_bfloat162* h = reinterpret_cast<const __nv_bfloat162*>(u);
        #pragma unroll
        for (int i = 0; i < 8; i++) {
            float2 t = __bfloat1622float2(h[i]);
            f[i * 2] = t.x; f[i * 2 + 1] = t.y;
        }
    }

    float m = f[0];
    #pragma unroll
    for (int i = 1; i < 16; i++) m = fmaxf(m, f[i]);
    red[tid] = m; __syncthreads();
    #pragma unroll
    for (int s = 128; s > 0; s >>= 1) {
        if (tid < s) red[tid] = fmaxf(red[tid], red[tid + s]);
        __syncthreads();
    }
    m = red[0];
    __syncthreads();

    float sum = 0.0f;
    #pragma unroll
    for (int i = 0; i < 16; i++) { f[i] = __expf(f[i] - m); sum += f[i]; }
    red[tid] = sum; __syncthreads();
    #pragma unroll
    for (int s = 128; s > 0; s >>= 1) {
        if (tid < s) red[tid] += red[tid + s];
        __syncthreads();
    }
    const float inv = 1.0f / red[0];

    __nv_bfloat162 h[8];
    #pragma unroll
    for (int i = 0; i < 8; i++)
        h[i] = __floats2bfloat162_rn(f[i * 2] * inv, f[i * 2 + 1] * inv);
    uint4 o[2];
    {
        uint32_t* w = reinterpret_cast<uint32_t*>(o);
        #pragma unroll
        for (int i = 0; i < 8; i++) w[i] = *(uint32_t*)&h[i];
    }
    p[tid * 2]     = o[0];
    p[tid * 2 + 1] = o[1];
}

// ---------------------------------------------------------------------------
extern "C" void kernel_launch(void* const* d_in, const int* in_sizes, int n_in,
                              void* d_out, int out_size)
{
    const float* x  = (const float*)d_in[0];
    const float* Wq = (const float*)d_in[1];
    const float* bq = (const float*)d_in[2];
    const float* Wk = (const float*)d_in[3];
    const float* bk = (const float*)d_in[4];
    const float* Wv = (const float*)d_in[5];
    const float* bv = (const float*)d_in[6];
    const float* Wp = (const float*)d_in[7];
    const float* bp = (const float*)d_in[8];
    float* out = (float*)d_out;

    __nv_bfloat16 *xb, *Q, *K, *V, *VT, *S, *C, *WT;
    cudaGetSymbolAddress((void**)&xb, g_xb);
    cudaGetSymbolAddress((void**)&Q,  g_Q);
    cudaGetSymbolAddress((void**)&K,  g_K);
    cudaGetSymbolAddress((void**)&V,  g_V);
    cudaGetSymbolAddress((void**)&VT, g_VT);
    cudaGetSymbolAddress((void**)&S,  g_S);
    cudaGetSymbolAddress((void**)&C,  g_C);
    cudaGetSymbolAddress((void**)&WT, g_WT);

    __nv_bfloat16* WqT = WT + 0 * (size_t)U_ * U_;
    __nv_bfloat16* WkT = WT + 1 * (size_t)U_ * U_;
    __nv_bfloat16* WvT = WT + 2 * (size_t)U_ * U_;
    __nv_bfloat16* WpT = WT + 3 * (size_t)U_ * U_;

    cudaFuncSetAttribute(gemm_bf16<true>,  cudaFuncAttributeMaxDynamicSharedMemorySize, SM_TOTAL);
    cudaFuncSetAttribute(gemm_bf16<false>, cudaFuncAttributeMaxDynamicSharedMemorySize, SM_TOTAL);

    const float scale = 1.0f / sqrtf((float)U_);

    // 0) convert x to bf16; transpose+convert weights
    conv_bf16<<<(M1 * U_ / 4 + 255) / 256, 256>>>(x, xb, (long long)M1 * U_);
    {
        dim3 tb(32, 8, 1), g(U_ / 32, U_ / 32, 1);
        wtransT<<<g, tb>>>(Wq, WqT, U_, U_);
        wtransT<<<g, tb>>>(Wk, WkT, U_, U_);
        wtransT<<<g, tb>>>(Wv, WvT, U_, U_);
        wtransT<<<g, tb>>>(Wp, WpT, U_, U_);
    }

    // 1) projections: [16384,512] = xb @ W^T (+b) -> bf16
    {
        dim3 g(U_ / BN, M1 / BM, 1);
        gemm_bf16<true><<<g, 256, SM_TOTAL>>>(xb, WqT, bq, nullptr, Q, M1, U_, U_, 0, 0, 0, 1.0f);
        gemm_bf16<true><<<g, 256, SM_TOTAL>>>(xb, WkT, bk, nullptr, K, M1, U_, U_, 0, 0, 0, 1.0f);
        gemm_bf16<true><<<g, 256, SM_TOTAL>>>(xb, WvT, bv, nullptr, V, M1, U_, U_, 0, 0, 0, 1.0f);
    }

    // 2) V^T per batch [512, 4096]
    {
        dim3 tb(32, 8, 1), g(U_ / 32, N_ / 32, B_);
        btransT<<<g, tb>>>(V, VT, N_, U_, (long long)N_ * U_, (long long)N_ * U_);
    }

    // 3) S[b] = scale * Q[b] @ K[b]^T -> bf16
    {
        dim3 g(N_ / BN, N_ / BM, B_);
        gemm_bf16<true><<<g, 256, SM_TOTAL>>>(Q, K, nullptr, nullptr, S,
                                              N_, N_, U_,
                                              (long long)N_ * U_, (long long)N_ * U_,
                                              (long long)N_ * N_, scale);
    }

    // 4) softmax rows in place
    softmax_bf16<<<B_ * N_, 256>>>(S);

    // 5) ctx[b] = P[b] @ V[b]   (B operand = V^T)
    {
        dim3 g(U_ / BN, N_ / BM, B_);
        gemm_bf16<true><<<g, 256, SM_TOTAL>>>(S, VT, nullptr, nullptr, C,
                                              N_, U_, N_,
                                              (long long)N_ * N_, (long long)N_ * U_,
                                              (long long)N_ * U_, 1.0f);
    }

    // 6) out = x + ctx @ Wp^T + bp  (fp32 out, residual)
    {
        dim3 g(U_ / BN, M1 / BM, 1);
        gemm_bf16<false><<<g, 256, SM_TOTAL>>>(C, WpT, bp, x, out, M1, U_, U_, 0, 0, 0, 1.0f);
    }
}